// round 5
// baseline (speedup 1.0000x reference)
#include <cuda_runtime.h>
#include <cuda_fp16.h>
#include <cstdint>

#define NE 8
#define NH 1024
#define NI 2048
#define NT 1024

// ---------------- device scratch (no allocations allowed) ----------------
__device__ int    g_counts[NE];
__device__ int    g_tok[NE * NT];
__device__ float  g_gate[NE * NT];
__device__ __half g_x16[(size_t)NT * NH];          // 2 MB
__device__ __half g_act[(size_t)NE * NT * NI];     // 33.5 MB

// ---------------- PTX helpers (base-PTX only: sm_100 safe) ----------------
__device__ __forceinline__ uint32_t smem_u32(const void* p) {
    uint32_t a;
    asm("{ .reg .u64 t; cvta.to.shared.u64 t, %1; cvt.u32.u64 %0, t; }" : "=r"(a) : "l"(p));
    return a;
}
__device__ __forceinline__ void ldm4(uint32_t* r, uint32_t addr) {
    asm volatile("ldmatrix.sync.aligned.m8n8.x4.shared.b16 {%0,%1,%2,%3}, [%4];"
                 : "=r"(r[0]), "=r"(r[1]), "=r"(r[2]), "=r"(r[3]) : "r"(addr));
}
__device__ __forceinline__ void mma16(float* c, const uint32_t* a, const uint32_t* b) {
    asm volatile(
        "mma.sync.aligned.m16n8k16.row.col.f32.f16.f16.f32 "
        "{%0,%1,%2,%3},{%4,%5,%6,%7},{%8,%9},{%0,%1,%2,%3};"
        : "+f"(c[0]), "+f"(c[1]), "+f"(c[2]), "+f"(c[3])
        : "r"(a[0]), "r"(a[1]), "r"(a[2]), "r"(a[3]), "r"(b[0]), "r"(b[1]));
}
__device__ __forceinline__ void cpa16(uint32_t dst, const void* src) {
    asm volatile("cp.async.cg.shared.global [%0], [%1], 16;" :: "r"(dst), "l"(src));
}
__device__ __forceinline__ void cp_commit() { asm volatile("cp.async.commit_group;"); }
template <int N> __device__ __forceinline__ void cp_wait() {
    asm volatile("cp.async.wait_group %0;" :: "n"(N));
}
__device__ __forceinline__ uint32_t pkh2(float a, float b) {
    __half2 t = __floats2half2_rn(a, b);
    return *reinterpret_cast<uint32_t*>(&t);
}

// smem tile geometry: 128 rows x 64 fp16 (=128B), padded row stride 144B
// A: 3-slot ring; B: 2-slot ring.
#define RSTRIDE 144
#define TILE_B  (128 * RSTRIDE)                    // 18432
#define OFF_A(i) (1024 + (i) * TILE_B)             // i in 0..2
#define OFF_B(j) (1024 + 3 * TILE_B + (j) * TILE_B)// j in 0..1
#define SMEM_TOT (1024 + 5 * TILE_B)               // 93184

// ---------------- kernel 0: zero out + counts, convert x -> fp16 ----------------
__global__ void prep_kernel(const float* __restrict__ x, float* __restrict__ out) {
    int i = blockIdx.x * 256 + threadIdx.x;
    if (i < NT * NH) { out[i] = 0.f; g_x16[i] = __float2half_rn(x[i]); }
    if (i < NE) g_counts[i] = 0;
}

// ---------------- kernel 1: router ----------------
__global__ void router_kernel(const float* __restrict__ logits) {
    int t = blockIdx.x * 256 + threadIdx.x;
    if (t >= NT) return;
    float b0 = -1e30f, b1 = -1e30f;
    int i0 = 0, i1 = 0;
#pragma unroll
    for (int ei = 0; ei < NE; ++ei) {
        float l = logits[t * NE + ei];
        if (l > b0) { b1 = b0; i1 = i0; b0 = l; i0 = ei; }
        else if (l > b1) { b1 = l; i1 = ei; }
    }
    float w0 = 1.f / (1.f + expf(b1 - b0));
    float w1 = 1.f - w0;
    int s0 = atomicAdd(&g_counts[i0], 1);
    g_tok[i0 * NT + s0] = t;  g_gate[i0 * NT + s0] = w0;
    int s1 = atomicAdd(&g_counts[i1], 1);
    g_tok[i1 * NT + s1] = t;  g_gate[i1 * NT + s1] = w1;
}

// ---------------- GEMM1: h = x @ w13^T + fused SwiGLU -> g_act (fp16) ----------------
// 3-stage A ring (cp.async, wait_group 1 => 2-stage latency cover), 2-stage B.
__global__ __launch_bounds__(256, 2)
void gemm1_k(const float* __restrict__ w13, const float* __restrict__ b13) {
    const int e   = blockIdx.z;
    const int cnt = g_counts[e];
    const int m0  = blockIdx.y * 128;
    if (m0 >= cnt) return;
    const int n0i = blockIdx.x * 64;
    const int S   = 16;

    extern __shared__ char sm[];
    const uint32_t smb = smem_u32(sm);
    const int tid = threadIdx.x, wid = tid >> 5, lane = tid & 31;
    const int lr = lane >> 2, lc = lane & 3;
    const int wm = (wid & 3) * 32, wn = (wid >> 2) * 32;
    int* sTok = (int*)sm;

    if (tid < 128) { int s = m0 + tid; sTok[tid] = (s < cnt) ? g_tok[e * NT + s] : 0; }
    __syncthreads();

    float acc[2][8][4];
#pragma unroll
    for (int mt = 0; mt < 2; ++mt)
#pragma unroll
        for (int nt = 0; nt < 8; ++nt)
#pragma unroll
            for (int i = 0; i < 4; ++i) acc[mt][nt][i] = 0.f;

    const int ar = tid >> 3,  ac = tid & 7;     // A loader: rows ar+32i, 16B chunk ac
    const int br = tid >> 4,  bc = tid & 15;    // B loader: rows br+16i, float4 chunk bc

    const uint32_t aoff = (uint32_t)((wm + (lane & 15)) * RSTRIDE + (lane >> 4) * 16);
    const uint32_t boff = (uint32_t)(((lane & 7) + ((lane >> 4) << 3)) * RSTRIDE
                                     + ((lane >> 3) & 1) * 16);

    // A row bases (gathered)
    const __half* arow0 = g_x16 + (size_t)sTok[ar] * NH;
    const __half* arow1 = g_x16 + (size_t)sTok[ar + 32] * NH;
    const __half* arow2 = g_x16 + (size_t)sTok[ar + 64] * NH;
    const __half* arow3 = g_x16 + (size_t)sTok[ar + 96] * NH;

    float4 b4[8];
    // ---- prologue: A(0), A(1) via cp.async; B(0) LDG->STS; B(1) LDG
#pragma unroll
    for (int st = 0; st < 2; ++st) {
        const int k0 = st * 64;
        cpa16(smb + OFF_A(st) + (ar)       * RSTRIDE + ac * 16, arow0 + k0 + ac * 8);
        cpa16(smb + OFF_A(st) + (ar + 32)  * RSTRIDE + ac * 16, arow1 + k0 + ac * 8);
        cpa16(smb + OFF_A(st) + (ar + 64)  * RSTRIDE + ac * 16, arow2 + k0 + ac * 8);
        cpa16(smb + OFF_A(st) + (ar + 96)  * RSTRIDE + ac * 16, arow3 + k0 + ac * 8);
        cp_commit();
    }
#pragma unroll
    for (int i = 0; i < 8; ++i) {
        int r = br + i * 16;
        int grow = (r < 64) ? (n0i + r) : (2048 + n0i + r - 64);
        b4[i] = *(const float4*)(w13 + ((size_t)e * 4096 + grow) * NH + bc * 4);
    }
#pragma unroll
    for (int i = 0; i < 8; ++i) {
        int r = br + i * 16;
        uint2 p = make_uint2(pkh2(b4[i].x, b4[i].y), pkh2(b4[i].z, b4[i].w));
        *(uint2*)(sm + OFF_B(0) + r * RSTRIDE + bc * 8) = p;
    }
#pragma unroll
    for (int i = 0; i < 8; ++i) {
        int r = br + i * 16;
        int grow = (r < 64) ? (n0i + r) : (2048 + n0i + r - 64);
        b4[i] = *(const float4*)(w13 + ((size_t)e * 4096 + grow) * NH + 64 + bc * 4);
    }
    cp_wait<1>();          // A(0) ready; A(1) may be in flight
    __syncthreads();

#pragma unroll 1
    for (int s = 0; s < S; ++s) {
        const uint32_t stA = OFF_A(s % 3), stB = OFF_B(s & 1);
        // issue A(s+2) into ring slot (s+2)%3
        if (s + 2 < S) {
            const int k0n = (s + 2) * 64;
            const uint32_t dst = smb + OFF_A((s + 2) % 3);
            cpa16(dst + (ar)      * RSTRIDE + ac * 16, arow0 + k0n + ac * 8);
            cpa16(dst + (ar + 32) * RSTRIDE + ac * 16, arow1 + k0n + ac * 8);
            cpa16(dst + (ar + 64) * RSTRIDE + ac * 16, arow2 + k0n + ac * 8);
            cpa16(dst + (ar + 96) * RSTRIDE + ac * 16, arow3 + k0n + ac * 8);
            cp_commit();
        }
        // STS B(s+1) (regs hold it), then LDG B(s+2)
        if (s + 1 < S) {
#pragma unroll
            for (int i = 0; i < 8; ++i) {
                int r = br + i * 16;
                uint2 p = make_uint2(pkh2(b4[i].x, b4[i].y), pkh2(b4[i].z, b4[i].w));
                *(uint2*)(sm + OFF_B((s + 1) & 1) + r * RSTRIDE + bc * 8) = p;
            }
        }
        if (s + 2 < S) {
            const int k0n2 = (s + 2) * 64;
#pragma unroll
            for (int i = 0; i < 8; ++i) {
                int r = br + i * 16;
                int grow = (r < 64) ? (n0i + r) : (2048 + n0i + r - 64);
                b4[i] = *(const float4*)(w13 + ((size_t)e * 4096 + grow) * NH + k0n2 + bc * 4);
            }
        }
        // compute current stage
#pragma unroll
        for (int k16 = 0; k16 < 4; ++k16) {
            uint32_t a[2][4];
            uint32_t abase = smb + stA + aoff + k16 * 32;
            ldm4(a[0], abase);
            ldm4(a[1], abase + 16 * RSTRIDE);
#pragma unroll
            for (int ntp = 0; ntp < 4; ++ntp) {
                int browoff = ((ntp >= 2) ? 64 : 0) + wn + ((ntp & 1) << 4);
                uint32_t b[4];
                ldm4(b, smb + stB + boff + browoff * RSTRIDE + k16 * 32);
                mma16(acc[0][ntp * 2],     a[0], b);
                mma16(acc[1][ntp * 2],     a[1], b);
                mma16(acc[0][ntp * 2 + 1], a[0], b + 2);
                mma16(acc[1][ntp * 2 + 1], a[1], b + 2);
            }
        }
        if (s < S - 2)      cp_wait<1>();   // A(s+1) landed, A(s+2) in flight
        else if (s == S - 2) cp_wait<0>();  // tail: A(S-1) must land
        __syncthreads();
    }

    // ---- epilogue: SwiGLU in registers, stage act tile in smem, coalesced store
    const float* bg = b13 + (size_t)e * 4096 + n0i;
    const float* bl = b13 + (size_t)e * 4096 + 2048 + n0i;
#pragma unroll
    for (int mt = 0; mt < 2; ++mt)
#pragma unroll
        for (int nt = 0; nt < 4; ++nt)
#pragma unroll
            for (int i = 0; i < 2; ++i) {
                int row = wm + mt * 16 + lr + i * 8;
                int col = wn + nt * 8 + lc * 2;
                float g0 = acc[mt][nt][i * 2 + 0] + bg[col];
                float g1 = acc[mt][nt][i * 2 + 1] + bg[col + 1];
                float l0 = acc[mt][nt + 4][i * 2 + 0] + bl[col];
                float l1 = acc[mt][nt + 4][i * 2 + 1] + bl[col + 1];
                float a0 = g0 * (1.f / (1.f + __expf(-1.702f * g0))) * (l0 + 1.0f);
                float a1 = g1 * (1.f / (1.f + __expf(-1.702f * g1))) * (l1 + 1.0f);
                *(uint32_t*)(sm + 1024 + row * RSTRIDE + col * 2) = pkh2(a0, a1);
            }
    __syncthreads();
#pragma unroll
    for (int i = 0; i < 4; ++i) {
        int idx = i * 256 + tid;
        int r = idx >> 3, c = idx & 7;
        int slot = m0 + r;
        if (slot < cnt) {
            uint4 v = *(uint4*)(sm + 1024 + r * RSTRIDE + c * 16);
            *(uint4*)(g_act + ((size_t)e * NT + slot) * NI + n0i + c * 8) = v;
        }
    }
}

// ---------------- GEMM2: y = act @ w2^T, gated atomic scatter ----------------
__global__ __launch_bounds__(256, 2)
void gemm2_k(const float* __restrict__ w2, const float* __restrict__ b2,
             float* __restrict__ out) {
    const int e   = blockIdx.z;
    const int cnt = g_counts[e];
    const int m0  = blockIdx.y * 128;
    if (m0 >= cnt) return;
    const int n0  = blockIdx.x * 128;
    const int S   = 32;

    extern __shared__ char sm[];
    const uint32_t smb = smem_u32(sm);
    const int tid = threadIdx.x, wid = tid >> 5, lane = tid & 31;
    const int lr = lane >> 2, lc = lane & 3;
    const int wm = (wid & 3) * 32, wn = (wid >> 2) * 64;
    int*   sTok = (int*)sm;
    float* sG   = (float*)(sm + 512);

    if (tid < 128) {
        int slot = m0 + tid;
        sTok[tid] = (slot < cnt) ? g_tok[e * NT + slot] : 0;
        sG[tid]   = (slot < cnt) ? g_gate[e * NT + slot] : 0.f;
    }
    __syncthreads();

    float acc[2][8][4];
#pragma unroll
    for (int mt = 0; mt < 2; ++mt)
#pragma unroll
        for (int nt = 0; nt < 8; ++nt)
#pragma unroll
            for (int i = 0; i < 4; ++i) acc[mt][nt][i] = 0.f;

    const int ar = tid >> 3,  ac = tid & 7;
    const int br = tid >> 4,  bc = tid & 15;
    const uint32_t aoff = (uint32_t)((wm + (lane & 15)) * RSTRIDE + (lane >> 4) * 16);
    const uint32_t boff = (uint32_t)(((lane & 7) + ((lane >> 4) << 3)) * RSTRIDE
                                     + ((lane >> 3) & 1) * 16);

    const __half* abase0 = g_act + ((size_t)e * NT + m0 + ar) * NI;

    float4 b4[8];
    // ---- prologue
#pragma unroll
    for (int st = 0; st < 2; ++st) {
        const int k0 = st * 64;
#pragma unroll
        for (int i = 0; i < 4; ++i) {
            int r = ar + i * 32;
            cpa16(smb + OFF_A(st) + r * RSTRIDE + ac * 16,
                  abase0 + (size_t)i * 32 * NI + k0 + ac * 8);
        }
        cp_commit();
    }
#pragma unroll
    for (int i = 0; i < 8; ++i) {
        int r = br + i * 16;
        b4[i] = *(const float4*)(w2 + ((size_t)e * NH + n0 + r) * NI + bc * 4);
    }
#pragma unroll
    for (int i = 0; i < 8; ++i) {
        int r = br + i * 16;
        uint2 p = make_uint2(pkh2(b4[i].x, b4[i].y), pkh2(b4[i].z, b4[i].w));
        *(uint2*)(sm + OFF_B(0) + r * RSTRIDE + bc * 8) = p;
    }
#pragma unroll
    for (int i = 0; i < 8; ++i) {
        int r = br + i * 16;
        b4[i] = *(const float4*)(w2 + ((size_t)e * NH + n0 + r) * NI + 64 + bc * 4);
    }
    cp_wait<1>();
    __syncthreads();

#pragma unroll 1
    for (int s = 0; s < S; ++s) {
        const uint32_t stA = OFF_A(s % 3), stB = OFF_B(s & 1);
        if (s + 2 < S) {
            const int k0n = (s + 2) * 64;
            const uint32_t dst = smb + OFF_A((s + 2) % 3);
#pragma unroll
            for (int i = 0; i < 4; ++i) {
                int r = ar + i * 32;
                cpa16(dst + r * RSTRIDE + ac * 16,
                      abase0 + (size_t)i * 32 * NI + k0n + ac * 8);
            }
            cp_commit();
        }
        if (s + 1 < S) {
#pragma unroll
            for (int i = 0; i < 8; ++i) {
                int r = br + i * 16;
                uint2 p = make_uint2(pkh2(b4[i].x, b4[i].y), pkh2(b4[i].z, b4[i].w));
                *(uint2*)(sm + OFF_B((s + 1) & 1) + r * RSTRIDE + bc * 8) = p;
            }
        }
        if (s + 2 < S) {
            const int k0n2 = (s + 2) * 64;
#pragma unroll
            for (int i = 0; i < 8; ++i) {
                int r = br + i * 16;
                b4[i] = *(const float4*)(w2 + ((size_t)e * NH + n0 + r) * NI + k0n2 + bc * 4);
            }
        }
#pragma unroll
        for (int k16 = 0; k16 < 4; ++k16) {
            uint32_t a[2][4];
            uint32_t abase = smb + stA + aoff + k16 * 32;
            ldm4(a[0], abase);
            ldm4(a[1], abase + 16 * RSTRIDE);
#pragma unroll
            for (int ntp = 0; ntp < 4; ++ntp) {
                uint32_t b[4];
                ldm4(b, smb + stB + boff + (wn + ntp * 16) * RSTRIDE + k16 * 32);
                mma16(acc[0][ntp * 2],     a[0], b);
                mma16(acc[1][ntp * 2],     a[1], b);
                mma16(acc[0][ntp * 2 + 1], a[0], b + 2);
                mma16(acc[1][ntp * 2 + 1], a[1], b + 2);
            }
        }
        if (s < S - 2)      cp_wait<1>();
        else if (s == S - 2) cp_wait<0>();
        __syncthreads();
    }

    // epilogue: out[tok, n0+col] += gate * (acc + b2)
    const float* bb = b2 + (size_t)e * NH + n0;
#pragma unroll
    for (int mt = 0; mt < 2; ++mt)
#pragma unroll
        for (int i = 0; i < 2; ++i) {
            int row = wm + mt * 16 + lr + i * 8;
            int slot = m0 + row;
            if (slot >= cnt) continue;
            int tok = sTok[row];
            float gate = sG[row];
            float* orow = out + (size_t)tok * NH + n0;
#pragma unroll
            for (int nt = 0; nt < 8; ++nt) {
                int col = wn + nt * 8 + lc * 2;
                atomicAdd(orow + col,     gate * (acc[mt][nt][i * 2 + 0] + bb[col]));
                atomicAdd(orow + col + 1, gate * (acc[mt][nt][i * 2 + 1] + bb[col + 1]));
            }
        }
}

// ---------------- host entry ----------------
extern "C" void kernel_launch(void* const* d_in, const int* in_sizes, int n_in,
                              void* d_out, int out_size) {
    const float* x      = (const float*)d_in[0];
    const float* logits = (const float*)d_in[1];
    const float* w13    = (const float*)d_in[2];
    const float* w2     = (const float*)d_in[3];
    const float* b13    = (const float*)d_in[4];
    const float* b2     = (const float*)d_in[5];
    float* out          = (float*)d_out;

    cudaFuncSetAttribute(gemm1_k, cudaFuncAttributeMaxDynamicSharedMemorySize, SMEM_TOT);
    cudaFuncSetAttribute(gemm2_k, cudaFuncAttributeMaxDynamicSharedMemorySize, SMEM_TOT);

    prep_kernel<<<(NT * NH + 255) / 256, 256>>>(x, out);
    router_kernel<<<(NT + 255) / 256, 256>>>(logits);
    gemm1_k<<<dim3(NI / 64, NT / 128, NE), 256, SMEM_TOT>>>(w13, b13);
    gemm2_k<<<dim3(NH / 128, NT / 128, NE), 256, SMEM_TOT>>>(w2, b2, out);
}